// round 3
// baseline (speedup 1.0000x reference)
#include <cuda_runtime.h>
#include <math.h>

#define Bb   2
#define Nn   1024
#define Dd   512
#define Hh   8
#define DHd  64
#define Ll   4
#define Mm   256
#define DFFd 2048
#define NTOK (Bb * Nn)   /* 2048 */
#define LNEPS 1e-5f

// ---------------- scratch (device globals: alloc-free) ----------------
__device__ float  g_x[NTOK * Dd];
__device__ float  g_y[NTOK * Dd];
__device__ float  g_q[NTOK * Dd];
__device__ float  g_k[NTOK * Dd];
__device__ float  g_v[NTOK * Dd];
__device__ float  g_o[NTOK * Dd];
__device__ float  g_feats[NTOK * 2 * Mm];
__device__ float  g_h[NTOK * DFFd];
__device__ float  g_s[(size_t)Bb * Hh * Nn * Nn];   // 64 MB scores
__device__ float  g_dm[(size_t)Bb * Nn * Nn];       // 8 MB distances
__device__ double g_red[2 * Bb];
__device__ float  g_invstd[Bb];

// ---------------- coordinate Fourier features ----------------
// grid: NTOK blocks, 256 threads (one per mode)
__global__ void feats_kernel(const float* __restrict__ coords,
                             const float* __restrict__ modes,
                             float* __restrict__ feats) {
    int t = blockIdx.x;
    int m = threadIdx.x;
    __shared__ float c[3];
    if (m < 3) c[m] = coords[t * 3 + m];
    __syncthreads();
    float ph = c[0] * modes[m * 3 + 0] + c[1] * modes[m * 3 + 1] + c[2] * modes[m * 3 + 2];
    float sv, cv;
    sincosf(ph, &sv, &cv);
    feats[(size_t)t * (2 * Mm) + m]      = cv;
    feats[(size_t)t * (2 * Mm) + Mm + m] = sv;
}

// ---------------- generic SGEMM: C[M x N] = A[M x K] @ W[K x N] (+bias)(+res)(gelu) ----
// BM=BN=64, BK=16, 256 threads, 4x4 per thread. All dims multiples of tiles.
#define GBM 64
#define GBN 64
#define GBK 16
__global__ void gemm_kernel(const float* __restrict__ A, const float* __restrict__ W,
                            const float* __restrict__ bias, const float* __restrict__ res,
                            float* __restrict__ C, int K, int Ncols, int act) {
    __shared__ float As[GBK][GBM + 1];
    __shared__ float Ws[GBK][GBN + 1];
    int tid  = threadIdx.x;
    int row0 = blockIdx.y * GBM;
    int col0 = blockIdx.x * GBN;
    float acc[4][4] = {};
    int ty = tid / 16, tx = tid % 16;

    for (int kt = 0; kt < K; kt += GBK) {
        #pragma unroll
        for (int i = 0; i < 4; i++) {
            int idx = tid + i * 256;        // 0..1023
            int r = idx / GBK, c = idx % GBK;
            As[c][r] = A[(size_t)(row0 + r) * K + kt + c];
        }
        #pragma unroll
        for (int i = 0; i < 4; i++) {
            int idx = tid + i * 256;
            int r = idx / GBN, c = idx % GBN;
            Ws[r][c] = W[(size_t)(kt + r) * Ncols + col0 + c];
        }
        __syncthreads();
        #pragma unroll
        for (int kk = 0; kk < GBK; kk++) {
            float a[4], b[4];
            #pragma unroll
            for (int i = 0; i < 4; i++) a[i] = As[kk][ty * 4 + i];
            #pragma unroll
            for (int j = 0; j < 4; j++) b[j] = Ws[kk][tx * 4 + j];
            #pragma unroll
            for (int i = 0; i < 4; i++)
                #pragma unroll
                for (int j = 0; j < 4; j++)
                    acc[i][j] = fmaf(a[i], b[j], acc[i][j]);
        }
        __syncthreads();
    }
    #pragma unroll
    for (int i = 0; i < 4; i++) {
        int r = row0 + ty * 4 + i;
        #pragma unroll
        for (int j = 0; j < 4; j++) {
            int c = col0 + tx * 4 + j;
            float v = acc[i][j];
            if (bias) v += bias[c];
            if (act == 1) v = 0.5f * v * (1.0f + erff(v * 0.70710678118654752f));
            if (res) v += res[(size_t)r * Ncols + c];
            C[(size_t)r * Ncols + c] = v;
        }
    }
}

// ---------------- layernorm: one block per row of D=512 ----------------
__global__ void ln_kernel(const float* __restrict__ x, const float* __restrict__ g,
                          const float* __restrict__ b, float* __restrict__ y) {
    int row = blockIdx.x;
    int t = threadIdx.x;
    const float* px = x + (size_t)row * Dd;
    float a0 = px[t], a1 = px[t + 256];
    __shared__ float red[256];
    red[t] = a0 + a1;
    __syncthreads();
    for (int o = 128; o > 0; o >>= 1) {
        if (t < o) red[t] += red[t + o];
        __syncthreads();
    }
    float mean = red[0] * (1.0f / Dd);
    float d0 = a0 - mean, d1 = a1 - mean;
    __syncthreads();
    red[t] = d0 * d0 + d1 * d1;
    __syncthreads();
    for (int o = 128; o > 0; o >>= 1) {
        if (t < o) red[t] += red[t + o];
        __syncthreads();
    }
    float var = red[0] * (1.0f / Dd);
    float r = rsqrtf(var + LNEPS);
    float* py = y + (size_t)row * Dd;
    py[t]       = d0 * r * g[t]       + b[t];
    py[t + 256] = d1 * r * g[t + 256] + b[t + 256];
}

// ---------------- pairwise distances + batch sum/sumsq ----------------
__global__ void zero_red_kernel(double* red) {
    if (threadIdx.x < 2 * Bb) red[threadIdx.x] = 0.0;
}

// grid (N/32, N/32, B), block (32,32)
__global__ void dist_kernel(const float* __restrict__ coords,
                            float* __restrict__ dmat, double* __restrict__ red) {
    int b = blockIdx.z;
    int i = blockIdx.y * 32 + threadIdx.y;
    int j = blockIdx.x * 32 + threadIdx.x;
    const float* cb = coords + (size_t)b * Nn * 3;
    float dx = cb[i * 3 + 0] - (cb[j * 3 + 0] + 1e-5f);
    float dy = cb[i * 3 + 1] - (cb[j * 3 + 1] + 1e-5f);
    float dz = cb[i * 3 + 2] - (cb[j * 3 + 2] + 1e-5f);
    float dd = sqrtf(dx * dx + dy * dy + dz * dz);
    dmat[((size_t)b * Nn + i) * Nn + j] = dd;

    __shared__ double sd[1024];
    int t = threadIdx.y * 32 + threadIdx.x;
    sd[t] = (double)dd;
    __syncthreads();
    for (int o = 512; o > 0; o >>= 1) {
        if (t < o) sd[t] += sd[t + o];
        __syncthreads();
    }
    if (t == 0) atomicAdd(&red[b * 2 + 0], sd[0]);
    __syncthreads();
    sd[t] = (double)dd * (double)dd;
    __syncthreads();
    for (int o = 512; o > 0; o >>= 1) {
        if (t < o) sd[t] += sd[t + o];
        __syncthreads();
    }
    if (t == 0) atomicAdd(&red[b * 2 + 1], sd[0]);
}

__global__ void dstd_kernel(const double* __restrict__ red, float* __restrict__ invstd) {
    int b = threadIdx.x;
    if (b < Bb) {
        double n = (double)Nn * (double)Nn;
        double mean = red[b * 2 + 0] / n;
        double var = (red[b * 2 + 1] - n * mean * mean) / (n - 1.0);
        invstd[b] = (float)(1.0 / sqrt(var));
    }
}

// ---------------- Q K^T with fused distance bias ----------------
// grid (N/32, N/32, B*H), 256 threads, 2x2 per thread
__global__ void qk_kernel(const float* __restrict__ q, const float* __restrict__ k,
                          const float* __restrict__ dmat, const float* __restrict__ temp,
                          const float* __restrict__ invstd, float* __restrict__ s, int layer) {
    int bh = blockIdx.z;
    int b = bh / Hh, h = bh % Hh;
    const float* Q = q + (size_t)b * Nn * Dd + h * DHd;
    const float* K = k + (size_t)b * Nn * Dd + h * DHd;
    __shared__ float Qs[32][DHd + 1];
    __shared__ float Ks[32][DHd + 1];
    int i0 = blockIdx.y * 32, j0 = blockIdx.x * 32;
    for (int t = threadIdx.x; t < 32 * DHd; t += 256) {
        int r = t / DHd, c = t % DHd;
        Qs[r][c] = Q[(size_t)(i0 + r) * Dd + c];
        Ks[r][c] = K[(size_t)(j0 + r) * Dd + c];
    }
    __syncthreads();
    int ty = threadIdx.x / 16, tx = threadIdx.x % 16;
    float acc00 = 0.f, acc01 = 0.f, acc10 = 0.f, acc11 = 0.f;
    #pragma unroll
    for (int kk = 0; kk < DHd; kk++) {
        float a0 = Qs[ty * 2 + 0][kk], a1 = Qs[ty * 2 + 1][kk];
        float b0 = Ks[tx * 2 + 0][kk], b1 = Ks[tx * 2 + 1][kk];
        acc00 = fmaf(a0, b0, acc00);
        acc01 = fmaf(a0, b1, acc01);
        acc10 = fmaf(a1, b0, acc10);
        acc11 = fmaf(a1, b1, acc11);
    }
    float tv = temp[layer * Hh + h];
    float coef = log1pf(expf(tv)) * invstd[b];
    const float scale = 0.125f;  // 1/sqrt(64)
    size_t sbase = (size_t)bh * Nn * Nn;
    size_t dbase = (size_t)b * Nn * Nn;
    #pragma unroll
    for (int i = 0; i < 2; i++) {
        int gi = i0 + ty * 2 + i;
        #pragma unroll
        for (int j = 0; j < 2; j++) {
            int gj = j0 + tx * 2 + j;
            float v = (i == 0 ? (j == 0 ? acc00 : acc01) : (j == 0 ? acc10 : acc11));
            s[sbase + (size_t)gi * Nn + gj] =
                v * scale - coef * dmat[dbase + (size_t)gi * Nn + gj];
        }
    }
}

// ---------------- row softmax over N=1024 ----------------
__global__ void softmax_kernel(float* __restrict__ s) {
    size_t row = blockIdx.x;
    float* p = s + row * (size_t)Nn;
    int t = threadIdx.x;
    float v0 = p[t], v1 = p[t + 256], v2 = p[t + 512], v3 = p[t + 768];
    __shared__ float red[256];
    red[t] = fmaxf(fmaxf(v0, v1), fmaxf(v2, v3));
    __syncthreads();
    for (int o = 128; o > 0; o >>= 1) {
        if (t < o) red[t] = fmaxf(red[t], red[t + o]);
        __syncthreads();
    }
    float m = red[0];
    v0 = expf(v0 - m); v1 = expf(v1 - m); v2 = expf(v2 - m); v3 = expf(v3 - m);
    __syncthreads();
    red[t] = v0 + v1 + v2 + v3;
    __syncthreads();
    for (int o = 128; o > 0; o >>= 1) {
        if (t < o) red[t] += red[t + o];
        __syncthreads();
    }
    float r = 1.0f / red[0];
    p[t] = v0 * r; p[t + 256] = v1 * r; p[t + 512] = v2 * r; p[t + 768] = v3 * r;
}

// ---------------- A @ V (batched over B*H) ----------------
// grid (N/64, B*H), 256 threads, 4x4 per thread, output 64 x 64(=DH)
__global__ void av_kernel(const float* __restrict__ s, const float* __restrict__ v,
                          float* __restrict__ o) {
    int bh = blockIdx.y;
    int b = bh / Hh, h = bh % Hh;
    const float* A = s + (size_t)bh * Nn * Nn;
    const float* V = v + (size_t)b * Nn * Dd + h * DHd;
    float* O = o + (size_t)b * Nn * Dd + h * DHd;
    __shared__ float As[32][64 + 1];   // [k][m]
    __shared__ float Vs[32][DHd + 1];  // [k][n]
    int i0 = blockIdx.x * 64;
    int tid = threadIdx.x;
    int ty = tid / 16, tx = tid % 16;
    float acc[4][4] = {};
    for (int kt = 0; kt < Nn; kt += 32) {
        #pragma unroll
        for (int i = 0; i < 8; i++) {
            int idx = tid + i * 256;       // 0..2047: A tile 64x32
            int r = idx / 32, c = idx % 32;
            As[c][r] = A[(size_t)(i0 + r) * Nn + kt + c];
        }
        #pragma unroll
        for (int i = 0; i < 8; i++) {
            int idx = tid + i * 256;       // V tile 32x64
            int r = idx / 64, c = idx % 64;
            Vs[r][c] = V[(size_t)(kt + r) * Dd + c];
        }
        __syncthreads();
        #pragma unroll
        for (int kk = 0; kk < 32; kk++) {
            float a[4], bb[4];
            #pragma unroll
            for (int i = 0; i < 4; i++) a[i] = As[kk][ty * 4 + i];
            #pragma unroll
            for (int j = 0; j < 4; j++) bb[j] = Vs[kk][tx * 4 + j];
            #pragma unroll
            for (int i = 0; i < 4; i++)
                #pragma unroll
                for (int j = 0; j < 4; j++)
                    acc[i][j] = fmaf(a[i], bb[j], acc[i][j]);
        }
        __syncthreads();
    }
    #pragma unroll
    for (int i = 0; i < 4; i++)
        #pragma unroll
        for (int j = 0; j < 4; j++)
            O[(size_t)(i0 + ty * 4 + i) * Dd + tx * 4 + j] = acc[i][j];
}

// ---------------- host launch ----------------
extern "C" void kernel_launch(void* const* d_in, const int* in_sizes, int n_in,
                              void* d_out, int out_size) {
    (void)in_sizes; (void)n_in; (void)out_size;
    const float* phi    = (const float*)d_in[0];
    const float* coords = (const float*)d_in[1];
    const float* modes  = (const float*)d_in[2];
    const float* We     = (const float*)d_in[3];
    const float* be     = (const float*)d_in[4];
    const float* wq     = (const float*)d_in[5];
    const float* bq     = (const float*)d_in[6];
    const float* wk     = (const float*)d_in[7];
    const float* bk     = (const float*)d_in[8];
    const float* wv     = (const float*)d_in[9];
    const float* bv     = (const float*)d_in[10];
    const float* wo     = (const float*)d_in[11];
    const float* bo     = (const float*)d_in[12];
    const float* temp   = (const float*)d_in[13];
    const float* ln1g   = (const float*)d_in[14];
    const float* ln1b   = (const float*)d_in[15];
    const float* ln2g   = (const float*)d_in[16];
    const float* ln2b   = (const float*)d_in[17];
    const float* w1     = (const float*)d_in[18];
    const float* b1     = (const float*)d_in[19];
    const float* w2     = (const float*)d_in[20];
    const float* b2     = (const float*)d_in[21];
    const float* fng    = (const float*)d_in[22];
    const float* fnb    = (const float*)d_in[23];
    float* out = (float*)d_out;

    float *x, *y, *q, *k, *v, *o, *feats, *hb, *s, *dm, *invstd;
    double* red;
    cudaGetSymbolAddress((void**)&x, g_x);
    cudaGetSymbolAddress((void**)&y, g_y);
    cudaGetSymbolAddress((void**)&q, g_q);
    cudaGetSymbolAddress((void**)&k, g_k);
    cudaGetSymbolAddress((void**)&v, g_v);
    cudaGetSymbolAddress((void**)&o, g_o);
    cudaGetSymbolAddress((void**)&feats, g_feats);
    cudaGetSymbolAddress((void**)&hb, g_h);
    cudaGetSymbolAddress((void**)&s, g_s);
    cudaGetSymbolAddress((void**)&dm, g_dm);
    cudaGetSymbolAddress((void**)&red, g_red);
    cudaGetSymbolAddress((void**)&invstd, g_invstd);

    // 1) Fourier features + input projection (x = phi + feats @ We + be)
    feats_kernel<<<NTOK, 256>>>(coords, modes, feats);
    gemm_kernel<<<dim3(Dd / GBN, NTOK / GBM), 256>>>(feats, We, be, phi, x, 2 * Mm, Dd, 0);

    // 2) distance matrix + per-batch inverse std (ddof=1)
    zero_red_kernel<<<1, 32>>>(red);
    dist_kernel<<<dim3(Nn / 32, Nn / 32, Bb), dim3(32, 32)>>>(coords, dm, red);
    dstd_kernel<<<1, 32>>>(red, invstd);

    for (int l = 0; l < Ll; l++) {
        const float* WQ = wq + (size_t)l * Dd * Dd;
        const float* WK = wk + (size_t)l * Dd * Dd;
        const float* WV = wv + (size_t)l * Dd * Dd;
        const float* WO = wo + (size_t)l * Dd * Dd;
        const float* W1 = w1 + (size_t)l * Dd * DFFd;
        const float* W2 = w2 + (size_t)l * DFFd * Dd;

        ln_kernel<<<NTOK, 256>>>(x, ln1g + l * Dd, ln1b + l * Dd, y);
        gemm_kernel<<<dim3(Dd / GBN, NTOK / GBM), 256>>>(y, WQ, bq + l * Dd, nullptr, q, Dd, Dd, 0);
        gemm_kernel<<<dim3(Dd / GBN, NTOK / GBM), 256>>>(y, WK, bk + l * Dd, nullptr, k, Dd, Dd, 0);
        gemm_kernel<<<dim3(Dd / GBN, NTOK / GBM), 256>>>(y, WV, bv + l * Dd, nullptr, v, Dd, Dd, 0);

        qk_kernel<<<dim3(Nn / 32, Nn / 32, Bb * Hh), 256>>>(q, k, dm, temp, invstd, s, l);
        softmax_kernel<<<Bb * Hh * Nn, 256>>>(s);
        av_kernel<<<dim3(Nn / 64, Bb * Hh), 256>>>(s, v, o);

        // x = x + o @ wo + bo
        gemm_kernel<<<dim3(Dd / GBN, NTOK / GBM), 256>>>(o, WO, bo + l * Dd, x, x, Dd, Dd, 0);

        // FFN
        ln_kernel<<<NTOK, 256>>>(x, ln2g + l * Dd, ln2b + l * Dd, y);
        gemm_kernel<<<dim3(DFFd / GBN, NTOK / GBM), 256>>>(y, W1, b1 + l * DFFd, nullptr, hb, Dd, DFFd, 1);
        gemm_kernel<<<dim3(Dd / GBN, NTOK / GBM), 256>>>(hb, W2, b2 + l * Dd, x, x, DFFd, Dd, 0);
    }

    // final layernorm -> output
    ln_kernel<<<NTOK, 256>>>(x, fng, fnb, out);
}

// round 4
// speedup vs baseline: 1.5409x; 1.5409x over previous
#include <cuda_runtime.h>
#include <math.h>

#define Bb   2
#define Nn   1024
#define Dd   512
#define Hh   8
#define DHd  64
#define Ll   4
#define Mm   256
#define DFFd 2048
#define NTOK (Bb * Nn)   /* 2048 */
#define LNEPS 1e-5f

// ---------------- scratch (device globals: alloc-free) ----------------
__device__ float  g_x[NTOK * Dd];
__device__ float  g_y[NTOK * Dd];
__device__ float  g_q[NTOK * Dd];
__device__ float  g_k[NTOK * Dd];
__device__ float  g_v[NTOK * Dd];
__device__ float  g_o[NTOK * Dd];
__device__ float  g_feats[NTOK * 2 * Mm];
__device__ float  g_h[NTOK * DFFd];
__device__ float  g_s[(size_t)Bb * Hh * Nn * Nn];   // 64 MB scores
__device__ float  g_dm[(size_t)Bb * Nn * Nn];       // 8 MB distances
__device__ double g_red[2 * Bb];
__device__ float  g_invstd[Bb];

// ---------------- packed fp32 FMA (FFMA2 path, full-rate on sm_103a) ----------
__device__ __forceinline__ void fma2(unsigned long long& d, unsigned long long a,
                                     unsigned long long b) {
    asm("fma.rn.f32x2 %0, %1, %2, %0;" : "+l"(d) : "l"(a), "l"(b));
}
__device__ __forceinline__ float2 u2f(unsigned long long u) {
    union { unsigned long long u; float2 f; } c; c.u = u; return c.f;
}

// ---------------- GEMM tiling constants ----------------
#define BM   128
#define BN   64
#define BK   16
#define ASTR (BM + 4)   // 132 floats: even (8B pairs) and 16B-aligned rows

// inner product over one smem buffer: 4 LDS.128 + 16 FMA2 per kk
#define GEMM_INNER(bufv)                                                          \
    _Pragma("unroll")                                                             \
    for (int kk = 0; kk < BK; kk++) {                                             \
        const float* ap = &As[bufv][kk][ty * 8];                                  \
        const float* bp = &Wsd[bufv][kk][tx * 8];                                 \
        ulonglong2 aa0 = *(const ulonglong2*)(ap);                                \
        ulonglong2 aa1 = *(const ulonglong2*)(ap + 4);                            \
        ulonglong2 bb0 = *(const ulonglong2*)(bp);                                \
        ulonglong2 bb1 = *(const ulonglong2*)(bp + 4);                            \
        fma2(acc[0][0], aa0.x, bb0.x); fma2(acc[0][1], aa0.x, bb0.y);             \
        fma2(acc[0][2], aa0.x, bb1.x); fma2(acc[0][3], aa0.x, bb1.y);             \
        fma2(acc[1][0], aa0.y, bb0.x); fma2(acc[1][1], aa0.y, bb0.y);             \
        fma2(acc[1][2], aa0.y, bb1.x); fma2(acc[1][3], aa0.y, bb1.y);             \
        fma2(acc[2][0], aa1.x, bb0.x); fma2(acc[2][1], aa1.x, bb0.y);             \
        fma2(acc[2][2], aa1.x, bb1.x); fma2(acc[2][3], aa1.x, bb1.y);             \
        fma2(acc[3][0], aa1.y, bb0.x); fma2(acc[3][1], aa1.y, bb0.y);             \
        fma2(acc[3][2], aa1.y, bb1.x); fma2(acc[3][3], aa1.y, bb1.y);             \
    }

#define STORE_A_TILE(bufv, v0, v1)                                                \
    As[bufv][akq * 4 + 0][ar] = v0.x; As[bufv][akq * 4 + 1][ar] = v0.y;           \
    As[bufv][akq * 4 + 2][ar] = v0.z; As[bufv][akq * 4 + 3][ar] = v0.w;           \
    As[bufv][akq * 4 + 0][ar + 64] = v1.x; As[bufv][akq * 4 + 1][ar + 64] = v1.y; \
    As[bufv][akq * 4 + 2][ar + 64] = v1.z; As[bufv][akq * 4 + 3][ar + 64] = v1.w;

#define STORE_W_TILE(bufv, v) {                                                   \
    float2* _p = (float2*)&Wsd[bufv][wr][wcq * 8];                                \
    _p[0] = make_float2(v.x, v.x); _p[1] = make_float2(v.y, v.y);                 \
    _p[2] = make_float2(v.z, v.z); _p[3] = make_float2(v.w, v.w); }

#define STORE_WT_TILE(bufv, v) {                                                  \
    *(float2*)&Wsd[bufv][wdq * 4 + 0][wc * 2] = make_float2(v.x, v.x);            \
    *(float2*)&Wsd[bufv][wdq * 4 + 1][wc * 2] = make_float2(v.y, v.y);            \
    *(float2*)&Wsd[bufv][wdq * 4 + 2][wc * 2] = make_float2(v.z, v.z);            \
    *(float2*)&Wsd[bufv][wdq * 4 + 3][wc * 2] = make_float2(v.w, v.w); }

// ---------------- main GEMM: C[M x N] = A[M x K] @ W[K x N] (+bias)(gelu)(+res) --
// 128x64 tile, 256 threads, per-thread 8x4 (M-pairs packed), double-buffered.
template<int ACT>   // 0: none, 1: exact GELU
__global__ void __launch_bounds__(256)
gemm_main(const float* __restrict__ A, int lda, long long sA,
          const float* __restrict__ W, int ldw, long long sW,
          float* __restrict__ C, int ldc, long long sC,
          const float* __restrict__ bias,
          const float* __restrict__ res, int ldres,
          int K)
{
    __shared__ float As[2][BK][ASTR];
    __shared__ float Wsd[2][BK][2 * BN];

    int z = blockIdx.z;
    A += (long long)z * sA; W += (long long)z * sW; C += (long long)z * sC;

    int tid  = threadIdx.x;
    int row0 = blockIdx.y * BM, col0 = blockIdx.x * BN;
    int ty = tid >> 4, tx = tid & 15;
    int ar = tid >> 2, akq = tid & 3;
    int wr = ty, wcq = tx;

    const float* A0 = A + (long long)(row0 + ar) * lda + akq * 4;
    const float* A1 = A + (long long)(row0 + ar + 64) * lda + akq * 4;
    const float* Wp = W + (long long)wr * ldw + col0 + wcq * 4;

    // prologue: tile 0
    float4 a0 = *(const float4*)A0;
    float4 a1 = *(const float4*)A1;
    float4 wv = *(const float4*)Wp;
    STORE_A_TILE(0, a0, a1);
    STORE_W_TILE(0, wv);
    __syncthreads();

    unsigned long long acc[4][4];
    #pragma unroll
    for (int i = 0; i < 4; i++)
        #pragma unroll
        for (int j = 0; j < 4; j++) acc[i][j] = 0ull;

    int nk = K / BK, buf = 0;
    for (int t = 0; t < nk; t++) {
        float4 na0, na1, nwv;
        bool pf = (t + 1 < nk);
        if (pf) {
            int kt = (t + 1) * BK;
            na0 = *(const float4*)(A0 + kt);
            na1 = *(const float4*)(A1 + kt);
            nwv = *(const float4*)(Wp + (long long)kt * ldw);
        }
        GEMM_INNER(buf);
        if (pf) {
            STORE_A_TILE(buf ^ 1, na0, na1);
            STORE_W_TILE(buf ^ 1, nwv);
            __syncthreads();
        }
        buf ^= 1;
    }

    // epilogue
    float bc[4] = {0.f, 0.f, 0.f, 0.f};
    if (bias) {
        float4 bv = *(const float4*)&bias[col0 + tx * 4];
        bc[0] = bv.x; bc[1] = bv.y; bc[2] = bv.z; bc[3] = bv.w;
    }
    #pragma unroll
    for (int i2 = 0; i2 < 4; i2++) {
        float2 p0 = u2f(acc[i2][0]), p1 = u2f(acc[i2][1]);
        float2 p2 = u2f(acc[i2][2]), p3 = u2f(acc[i2][3]);
        int r = row0 + ty * 8 + i2 * 2;
        float4 v0 = make_float4(p0.x + bc[0], p1.x + bc[1], p2.x + bc[2], p3.x + bc[3]);
        float4 v1 = make_float4(p0.y + bc[0], p1.y + bc[1], p2.y + bc[2], p3.y + bc[3]);
        if (ACT == 1) {
            v0.x = 0.5f * v0.x * (1.0f + erff(v0.x * 0.70710678118654752f));
            v0.y = 0.5f * v0.y * (1.0f + erff(v0.y * 0.70710678118654752f));
            v0.z = 0.5f * v0.z * (1.0f + erff(v0.z * 0.70710678118654752f));
            v0.w = 0.5f * v0.w * (1.0f + erff(v0.w * 0.70710678118654752f));
            v1.x = 0.5f * v1.x * (1.0f + erff(v1.x * 0.70710678118654752f));
            v1.y = 0.5f * v1.y * (1.0f + erff(v1.y * 0.70710678118654752f));
            v1.z = 0.5f * v1.z * (1.0f + erff(v1.z * 0.70710678118654752f));
            v1.w = 0.5f * v1.w * (1.0f + erff(v1.w * 0.70710678118654752f));
        }
        if (res) {
            float4 r0 = *(const float4*)&res[(long long)r * ldres + col0 + tx * 4];
            float4 r1 = *(const float4*)&res[(long long)(r + 1) * ldres + col0 + tx * 4];
            v0.x += r0.x; v0.y += r0.y; v0.z += r0.z; v0.w += r0.w;
            v1.x += r1.x; v1.y += r1.y; v1.z += r1.z; v1.w += r1.w;
        }
        *(float4*)&C[(long long)r * ldc + col0 + tx * 4] = v0;
        *(float4*)&C[(long long)(r + 1) * ldc + col0 + tx * 4] = v1;
    }
}

// ---------------- Q K^T with fused distance bias (B transposed in smem) ----------
// grid (Nn/BN, Nn/BM, B*H): scores[i0..i0+128][j0..j0+64], K-dim = 64
__global__ void __launch_bounds__(256)
qk_gemm(const float* __restrict__ q, const float* __restrict__ kmat,
        const float* __restrict__ dmat, const float* __restrict__ temp,
        const float* __restrict__ invstd, float* __restrict__ s, int layer)
{
    __shared__ float As[2][BK][ASTR];
    __shared__ float Wsd[2][BK][2 * BN];

    int bh = blockIdx.z, b = bh >> 3, h = bh & 7;
    const float* A  = q    + (long long)b * Nn * Dd + h * DHd;
    const float* Km = kmat + (long long)b * Nn * Dd + h * DHd;

    int tid = threadIdx.x;
    int i0 = blockIdx.y * BM, j0 = blockIdx.x * BN;
    int ty = tid >> 4, tx = tid & 15;
    int ar = tid >> 2, akq = tid & 3;
    int wc = tid >> 2, wdq = tid & 3;   // K tile: col = token j (0..63), dq = d-quad

    const float* A0 = A + (long long)(i0 + ar) * Dd + akq * 4;
    const float* A1 = A + (long long)(i0 + ar + 64) * Dd + akq * 4;
    const float* Kp = Km + (long long)(j0 + wc) * Dd + wdq * 4;

    float4 a0 = *(const float4*)A0;
    float4 a1 = *(const float4*)A1;
    float4 kv = *(const float4*)Kp;
    STORE_A_TILE(0, a0, a1);
    STORE_WT_TILE(0, kv);
    __syncthreads();

    unsigned long long acc[4][4];
    #pragma unroll
    for (int i = 0; i < 4; i++)
        #pragma unroll
        for (int j = 0; j < 4; j++) acc[i][j] = 0ull;

    const int nk = DHd / BK;  // 4
    int buf = 0;
    #pragma unroll
    for (int t = 0; t < nk; t++) {
        float4 na0, na1, nkv;
        bool pf = (t + 1 < nk);
        if (pf) {
            int kt = (t + 1) * BK;
            na0 = *(const float4*)(A0 + kt);
            na1 = *(const float4*)(A1 + kt);
            nkv = *(const float4*)(Kp + kt);
        }
        GEMM_INNER(buf);
        if (pf) {
            STORE_A_TILE(buf ^ 1, na0, na1);
            STORE_WT_TILE(buf ^ 1, nkv);
            __syncthreads();
        }
        buf ^= 1;
    }

    float tv = temp[layer * Hh + h];
    float sp = (tv > 20.f) ? tv : log1pf(expf(tv));
    float coef = sp * invstd[b];
    const float scale = 0.125f;  // 1/sqrt(64)

    #pragma unroll
    for (int i2 = 0; i2 < 4; i2++) {
        float2 p0 = u2f(acc[i2][0]), p1 = u2f(acc[i2][1]);
        float2 p2 = u2f(acc[i2][2]), p3 = u2f(acc[i2][3]);
        int r = i0 + ty * 8 + i2 * 2;
        float4 d0 = *(const float4*)&dmat[((long long)b * Nn + r) * Nn + j0 + tx * 4];
        float4 d1 = *(const float4*)&dmat[((long long)b * Nn + r + 1) * Nn + j0 + tx * 4];
        float4 v0 = make_float4(p0.x * scale - coef * d0.x, p1.x * scale - coef * d0.y,
                                p2.x * scale - coef * d0.z, p3.x * scale - coef * d0.w);
        float4 v1 = make_float4(p0.y * scale - coef * d1.x, p1.y * scale - coef * d1.y,
                                p2.y * scale - coef * d1.z, p3.y * scale - coef * d1.w);
        *(float4*)&s[((long long)bh * Nn + r) * Nn + j0 + tx * 4] = v0;
        *(float4*)&s[((long long)bh * Nn + r + 1) * Nn + j0 + tx * 4] = v1;
    }
}

// ---------------- A @ V (batched over B*H): O[128 x 64] tiles, K = 1024 ----------
__global__ void __launch_bounds__(256)
av_gemm(const float* __restrict__ s, const float* __restrict__ v, float* __restrict__ o)
{
    __shared__ float As[2][BK][ASTR];
    __shared__ float Wsd[2][BK][2 * BN];

    int bh = blockIdx.z, b = bh >> 3, h = bh & 7;
    const float* A = s + (long long)bh * Nn * Nn;
    const float* V = v + (long long)b * Nn * Dd + h * DHd;
    float*       O = o + (long long)b * Nn * Dd + h * DHd;

    int tid = threadIdx.x;
    int row0 = blockIdx.y * BM;
    int ty = tid >> 4, tx = tid & 15;
    int ar = tid >> 2, akq = tid & 3;
    int wr = ty, wcq = tx;

    const float* A0 = A + (long long)(row0 + ar) * Nn + akq * 4;
    const float* A1 = A + (long long)(row0 + ar + 64) * Nn + akq * 4;
    const float* Wp = V + (long long)wr * Dd + wcq * 4;

    float4 a0 = *(const float4*)A0;
    float4 a1 = *(const float4*)A1;
    float4 wv = *(const float4*)Wp;
    STORE_A_TILE(0, a0, a1);
    STORE_W_TILE(0, wv);
    __syncthreads();

    unsigned long long acc[4][4];
    #pragma unroll
    for (int i = 0; i < 4; i++)
        #pragma unroll
        for (int j = 0; j < 4; j++) acc[i][j] = 0ull;

    const int nk = Nn / BK;  // 64
    int buf = 0;
    for (int t = 0; t < nk; t++) {
        float4 na0, na1, nwv;
        bool pf = (t + 1 < nk);
        if (pf) {
            int kt = (t + 1) * BK;
            na0 = *(const float4*)(A0 + kt);
            na1 = *(const float4*)(A1 + kt);
            nwv = *(const float4*)(Wp + (long long)kt * Dd);
        }
        GEMM_INNER(buf);
        if (pf) {
            STORE_A_TILE(buf ^ 1, na0, na1);
            STORE_W_TILE(buf ^ 1, nwv);
            __syncthreads();
        }
        buf ^= 1;
    }

    #pragma unroll
    for (int i2 = 0; i2 < 4; i2++) {
        float2 p0 = u2f(acc[i2][0]), p1 = u2f(acc[i2][1]);
        float2 p2 = u2f(acc[i2][2]), p3 = u2f(acc[i2][3]);
        int r = row0 + ty * 8 + i2 * 2;
        *(float4*)&O[(long long)r * Dd + tx * 4] = make_float4(p0.x, p1.x, p2.x, p3.x);
        *(float4*)&O[(long long)(r + 1) * Dd + tx * 4] = make_float4(p0.y, p1.y, p2.y, p3.y);
    }
}

// ---------------- coordinate Fourier features ----------------
__global__ void feats_kernel(const float* __restrict__ coords,
                             const float* __restrict__ modes,
                             float* __restrict__ feats) {
    int t = blockIdx.x;
    int m = threadIdx.x;
    __shared__ float c[3];
    if (m < 3) c[m] = coords[t * 3 + m];
    __syncthreads();
    float ph = c[0] * modes[m * 3 + 0] + c[1] * modes[m * 3 + 1] + c[2] * modes[m * 3 + 2];
    float sv, cv;
    sincosf(ph, &sv, &cv);
    feats[(size_t)t * (2 * Mm) + m]      = cv;
    feats[(size_t)t * (2 * Mm) + Mm + m] = sv;
}

// ---------------- layernorm: one block per row of D=512 ----------------
__global__ void ln_kernel(const float* __restrict__ x, const float* __restrict__ g,
                          const float* __restrict__ b, float* __restrict__ y) {
    int row = blockIdx.x;
    int t = threadIdx.x;
    const float* px = x + (size_t)row * Dd;
    float a0 = px[t], a1 = px[t + 256];
    __shared__ float red[256];
    red[t] = a0 + a1;
    __syncthreads();
    for (int o = 128; o > 0; o >>= 1) {
        if (t < o) red[t] += red[t + o];
        __syncthreads();
    }
    float mean = red[0] * (1.0f / Dd);
    float d0 = a0 - mean, d1 = a1 - mean;
    __syncthreads();
    red[t] = d0 * d0 + d1 * d1;
    __syncthreads();
    for (int o = 128; o > 0; o >>= 1) {
        if (t < o) red[t] += red[t + o];
        __syncthreads();
    }
    float var = red[0] * (1.0f / Dd);
    float r = rsqrtf(var + LNEPS);
    float* py = y + (size_t)row * Dd;
    py[t]       = d0 * r * g[t]       + b[t];
    py[t + 256] = d1 * r * g[t + 256] + b[t + 256];
}

// ---------------- pairwise distances (store only) ----------------
__global__ void dist_kernel(const float* __restrict__ coords, float* __restrict__ dmat) {
    int b = blockIdx.z;
    int i = blockIdx.y * 32 + threadIdx.y;
    int j = blockIdx.x * 32 + threadIdx.x;
    const float* cb = coords + (size_t)b * Nn * 3;
    float dx = cb[i * 3 + 0] - (cb[j * 3 + 0] + 1e-5f);
    float dy = cb[i * 3 + 1] - (cb[j * 3 + 1] + 1e-5f);
    float dz = cb[i * 3 + 2] - (cb[j * 3 + 2] + 1e-5f);
    dmat[((size_t)b * Nn + i) * Nn + j] = sqrtf(dx * dx + dy * dy + dz * dz);
}

__global__ void zero_red_kernel(double* red) {
    if (threadIdx.x < 2 * Bb) red[threadIdx.x] = 0.0;
}

// grid (128, Bb), 256 threads: grid-stride double reduction of sum / sumsq
__global__ void dist_reduce_kernel(const float* __restrict__ dmat, double* __restrict__ red) {
    int z = blockIdx.y;
    const float* p = dmat + (size_t)z * Nn * Nn;
    double s1 = 0.0, s2 = 0.0;
    for (int i = blockIdx.x * blockDim.x + threadIdx.x; i < Nn * Nn;
         i += gridDim.x * blockDim.x) {
        double d = (double)p[i];
        s1 += d;
        s2 += d * d;
    }
    for (int o = 16; o > 0; o >>= 1) {
        s1 += __shfl_down_sync(0xffffffffu, s1, o);
        s2 += __shfl_down_sync(0xffffffffu, s2, o);
    }
    __shared__ double sh1[8], sh2[8];
    int w = threadIdx.x >> 5, ln = threadIdx.x & 31;
    if (ln == 0) { sh1[w] = s1; sh2[w] = s2; }
    __syncthreads();
    if (threadIdx.x == 0) {
        double t1 = 0.0, t2 = 0.0;
        for (int i = 0; i < 8; i++) { t1 += sh1[i]; t2 += sh2[i]; }
        atomicAdd(&red[z * 2 + 0], t1);
        atomicAdd(&red[z * 2 + 1], t2);
    }
}

__global__ void dstd_kernel(const double* __restrict__ red, float* __restrict__ invstd) {
    int b = threadIdx.x;
    if (b < Bb) {
        double n = (double)Nn * (double)Nn;
        double mean = red[b * 2 + 0] / n;
        double var = (red[b * 2 + 1] - n * mean * mean) / (n - 1.0);
        invstd[b] = (float)(1.0 / sqrt(var));
    }
}

// ---------------- row softmax over N=1024 ----------------
__global__ void softmax_kernel(float* __restrict__ s) {
    size_t row = blockIdx.x;
    float* p = s + row * (size_t)Nn;
    int t = threadIdx.x;
    float v0 = p[t], v1 = p[t + 256], v2 = p[t + 512], v3 = p[t + 768];
    __shared__ float red[256];
    red[t] = fmaxf(fmaxf(v0, v1), fmaxf(v2, v3));
    __syncthreads();
    for (int o = 128; o > 0; o >>= 1) {
        if (t < o) red[t] = fmaxf(red[t], red[t + o]);
        __syncthreads();
    }
    float m = red[0];
    v0 = expf(v0 - m); v1 = expf(v1 - m); v2 = expf(v2 - m); v3 = expf(v3 - m);
    __syncthreads();
    red[t] = v0 + v1 + v2 + v3;
    __syncthreads();
    for (int o = 128; o > 0; o >>= 1) {
        if (t < o) red[t] += red[t + o];
        __syncthreads();
    }
    float r = 1.0f / red[0];
    p[t] = v0 * r; p[t + 256] = v1 * r; p[t + 512] = v2 * r; p[t + 768] = v3 * r;
}

// ---------------- host launch ----------------
extern "C" void kernel_launch(void* const* d_in, const int* in_sizes, int n_in,
                              void* d_out, int out_size) {
    (void)in_sizes; (void)n_in; (void)out_size;
    const float* phi    = (const float*)d_in[0];
    const float* coords = (const float*)d_in[1];
    const float* modes  = (const float*)d_in[2];
    const float* We     = (const float*)d_in[3];
    const float* be     = (const float*)d_in[4];
    const float* wq     = (const float*)d_in[5];
    const float* bq     = (const float*)d_in[6];
    const float* wk     = (const float*)d_in[7];
    const float* bk     = (const float*)d_in[8];
    const float* wv     = (const float*)d_in[9];
    const float* bv     = (const float*)d_in[10];
    const float* wo     = (const float*)d_in[11];
    const float* bo     = (const float*)d_in[12];
    const float* temp   = (const float*)d_in[13];
    const float* ln1g   = (const float*)d_in[14];
    const float* ln1b   = (const float*)d_in[15];
    const float* ln2g   = (const float*)d_in[16];
    const float* ln2b   = (const float*)d_in[17];
    const float* w1     = (const float*)d_in[18];
    const float* b1     = (const float*)d_in[19];
    const float* w2     = (const float*)d_in[20];
    const float* b2     = (const float*)d_in[21];
    const float* fng    = (const float*)d_in[22];
    const float* fnb    = (const float*)d_in[23];
    float* out = (float*)d_out;

    float *x, *y, *q, *k, *v, *o, *feats, *hb, *s, *dm, *invstd;
    double* red;
    cudaGetSymbolAddress((void**)&x, g_x);
    cudaGetSymbolAddress((void**)&y, g_y);
    cudaGetSymbolAddress((void**)&q, g_q);
    cudaGetSymbolAddress((void**)&k, g_k);
    cudaGetSymbolAddress((void**)&v, g_v);
    cudaGetSymbolAddress((void**)&o, g_o);
    cudaGetSymbolAddress((void**)&feats, g_feats);
    cudaGetSymbolAddress((void**)&hb, g_h);
    cudaGetSymbolAddress((void**)&s, g_s);
    cudaGetSymbolAddress((void**)&dm, g_dm);
    cudaGetSymbolAddress((void**)&red, g_red);
    cudaGetSymbolAddress((void**)&invstd, g_invstd);

    // 1) Fourier features + input projection: x = phi + feats @ We + be
    feats_kernel<<<NTOK, 256>>>(coords, modes, feats);
    gemm_main<0><<<dim3(Dd / BN, NTOK / BM, 1), 256>>>(
        feats, 2 * Mm, 0, We, Dd, 0, x, Dd, 0, be, phi, Dd, 2 * Mm);

    // 2) distance matrix + per-batch inverse std (ddof=1)
    dist_kernel<<<dim3(Nn / 32, Nn / 32, Bb), dim3(32, 32)>>>(coords, dm);
    zero_red_kernel<<<1, 32>>>(red);
    dist_reduce_kernel<<<dim3(128, Bb), 256>>>(dm, red);
    dstd_kernel<<<1, 32>>>(red, invstd);

    for (int l = 0; l < Ll; l++) {
        const float* WQ = wq + (size_t)l * Dd * Dd;
        const float* WK = wk + (size_t)l * Dd * Dd;
        const float* WV = wv + (size_t)l * Dd * Dd;
        const float* WO = wo + (size_t)l * Dd * Dd;
        const float* W1 = w1 + (size_t)l * Dd * DFFd;
        const float* W2 = w2 + (size_t)l * DFFd * Dd;

        ln_kernel<<<NTOK, 256>>>(x, ln1g + l * Dd, ln1b + l * Dd, y);
        gemm_main<0><<<dim3(Dd / BN, NTOK / BM, 1), 256>>>(
            y, Dd, 0, WQ, Dd, 0, q, Dd, 0, bq + l * Dd, nullptr, 0, Dd);
        gemm_main<0><<<dim3(Dd / BN, NTOK / BM, 1), 256>>>(
            y, Dd, 0, WK, Dd, 0, k, Dd, 0, bk + l * Dd, nullptr, 0, Dd);
        gemm_main<0><<<dim3(Dd / BN, NTOK / BM, 1), 256>>>(
            y, Dd, 0, WV, Dd, 0, v, Dd, 0, bv + l * Dd, nullptr, 0, Dd);

        qk_gemm<<<dim3(Nn / BN, Nn / BM, Bb * Hh), 256>>>(q, k, dm, temp, invstd, s, l);
        softmax_kernel<<<Bb * Hh * Nn, 256>>>(s);
        av_gemm<<<dim3(1, Nn / BM, Bb * Hh), 256>>>(s, v, o);

        // x = x + o @ wo + bo
        gemm_main<0><<<dim3(Dd / BN, NTOK / BM, 1), 256>>>(
            o, Dd, 0, WO, Dd, 0, x, Dd, 0, bo + l * Dd, x, Dd, Dd);

        // FFN
        ln_kernel<<<NTOK, 256>>>(x, ln2g + l * Dd, ln2b + l * Dd, y);
        gemm_main<1><<<dim3(DFFd / BN, NTOK / BM, 1), 256>>>(
            y, Dd, 0, W1, DFFd, 0, hb, DFFd, 0, b1 + l * DFFd, nullptr, 0, Dd);
        gemm_main<0><<<dim3(Dd / BN, NTOK / BM, 1), 256>>>(
            hb, DFFd, 0, W2, Dd, 0, x, Dd, 0, b2 + l * Dd, x, Dd, DFFd);
    }

    // final layernorm -> output
    ln_kernel<<<NTOK, 256>>>(x, fng, fnb, out);
}